// round 8
// baseline (speedup 1.0000x reference)
#include <cuda_runtime.h>
#include <cuda_bf16.h>
#include <cstdint>

#define N_NODES 50000
#define E_EDGES 800000
#define NB_SCAN 196   // ceil(50000/256)
#define NB_CSR  296   // 2 blocks/SM * 148 SMs, one wave

// ---------------- device scratch (static, no allocs) ----------------
// P layout per node (256 floats):
//   dst region  [0,128):   channel c -> {fd,sd} at offset 2c
//   src region  [128,256): channel c -> {fs,ss} at offset 128+2c
__device__ __align__(16) float  d_P[(size_t)N_NODES * 256];
__device__ __align__(16) float  d_y0[(size_t)N_NODES * 64];
__device__ __align__(16) float  d_y1[(size_t)N_NODES * 64];
__device__ int    d_src[E_EDGES];
__device__ int    d_dst[E_EDGES];
__device__ int    d_deg[N_NODES];
__device__ int    d_fill[N_NODES];
__device__ int    d_rowptr[N_NODES + 1];
__device__ int    d_bsum[NB_SCAN];
__device__ int    d_boff[NB_SCAN];
__device__ int    d_esrc[E_EDGES];
__device__ __align__(16) float  d_ea_s[(size_t)E_EDGES * 16]; // edge_attr in CSR order
__device__ __align__(16) float  d_Wnode[2][64 * 256];         // packed-column node weights
__device__ __align__(16) float  d_WqT[2][128 * 16];           // edge weights [chan][k] (chan<64 f, else s)
__device__ float  d_bias2[2][256];
__device__ float  d_psum[NB_CSR * 64];
__device__ float  d_psq[NB_CSR * 64];
__device__ __align__(16) float  d_scale[2][64];
__device__ __align__(16) float  d_shift[2][64];
__device__ int    d_bound[65];
__device__ int    d_ei64;
__device__ int    d_b64;

__device__ __forceinline__ float sigmoid_f(float x) {
    float t;
    asm("tanh.approx.f32 %0, %1;" : "=f"(t) : "f"(x * 0.5f));
    return fmaf(0.5f, t, 0.5f);
}
__device__ __forceinline__ float softplus_f(float x) {
    return (x > 20.f) ? x : __logf(1.f + __expf(x));
}
__device__ __forceinline__ uint64_t fma2(uint64_t a, uint64_t b, uint64_t c) {
    uint64_t d;
    asm("fma.rn.f32x2 %0, %1, %2, %3;" : "=l"(d) : "l"(a), "l"(b), "l"(c));
    return d;
}
__device__ __forceinline__ float2 unpack2(uint64_t v) {
    float2 r;
    asm("mov.b64 {%0, %1}, %2;" : "=f"(r.x), "=f"(r.y) : "l"(v));
    return r;
}

// ---------------- zero counters + dtype detection ----------------
__global__ void zero_detect_kernel(const int* __restrict__ ei32, const int* __restrict__ b32) {
    int stride = gridDim.x * blockDim.x;
    for (int i = blockIdx.x * blockDim.x + threadIdx.x; i < N_NODES; i += stride) {
        d_deg[i] = 0; d_fill[i] = 0;
    }
    if (blockIdx.x == 0 && threadIdx.x == 0) {
        int o = 0;
        #pragma unroll
        for (int i = 1; i < 64; i += 2) o |= ei32[i];
        d_ei64 = (o == 0) ? 1 : 0;
        d_b64 = (b32[N_NODES - 1] == 0) ? 1 : 0;
    }
}

// ---------------- prep: decode+clamp indices (+hist), pack weights ----------------
__global__ void prep_kernel(const void* __restrict__ ei_raw,
                            const float* __restrict__ Wf0, const float* __restrict__ Ws0,
                            const float* __restrict__ bf0, const float* __restrict__ bs0,
                            const float* __restrict__ Wf1, const float* __restrict__ Ws1,
                            const float* __restrict__ bf1, const float* __restrict__ bs1) {
    int stride = gridDim.x * blockDim.x;
    int gid = blockIdx.x * blockDim.x + threadIdx.x;
    const int ei64 = d_ei64;
    const long long* eL = (const long long*)ei_raw;
    const int*       eI = (const int*)ei_raw;
    for (int i = gid; i < E_EDGES; i += stride) {
        int s, d;
        if (ei64) { s = (int)eL[i]; d = (int)eL[E_EDGES + i]; }
        else      { s = eI[i];      d = eI[E_EDGES + i]; }
        s = min(max(s, 0), N_NODES - 1);
        d = min(max(d, 0), N_NODES - 1);
        d_src[i] = s;
        d_dst[i] = d;
        atomicAdd(&d_deg[d], 1);
    }
    for (int i = gid; i < 2 * 64 * 144; i += stride) {
        int l = i / 9216; int r = i % 9216; int j = r / 144; int k = r % 144;
        const float* Wf = l ? Wf1 : Wf0;
        const float* Ws = l ? Ws1 : Ws0;
        float wf = Wf[j * 144 + k], ws = Ws[j * 144 + k];
        if (k < 64) {
            d_Wnode[l][k * 256 + 2 * j]     = wf;    // fd
            d_Wnode[l][k * 256 + 2 * j + 1] = ws;    // sd
        } else if (k < 128) {
            int kk = k - 64;
            d_Wnode[l][kk * 256 + 128 + 2 * j]     = wf;  // fs
            d_Wnode[l][kk * 256 + 128 + 2 * j + 1] = ws;  // ss
        } else {
            int kk = k - 128;
            d_WqT[l][j * 16 + kk]        = wf;
            d_WqT[l][(64 + j) * 16 + kk] = ws;
        }
    }
    for (int i = gid; i < 2 * 64; i += stride) {
        int l = i >> 6; int j = i & 63;
        const float* bf = l ? bf1 : bf0;
        const float* bs = l ? bs1 : bs0;
        d_bias2[l][2 * j]           = bf[j];
        d_bias2[l][2 * j + 1]       = bs[j];
        d_bias2[l][128 + 2 * j]     = 0.f;
        d_bias2[l][128 + 2 * j + 1] = 0.f;
    }
}

// ---------------- CSR scan: 3 small kernels ----------------
__global__ void scan1_kernel() {
    __shared__ int sh[256];
    int t = threadIdx.x;
    int i = blockIdx.x * 256 + t;
    sh[t] = (i < N_NODES) ? d_deg[i] : 0;
    __syncthreads();
    for (int off = 128; off > 0; off >>= 1) {
        if (t < off) sh[t] += sh[t + off];
        __syncthreads();
    }
    if (t == 0) d_bsum[blockIdx.x] = sh[0];
}

__global__ void scan2_kernel() {
    __shared__ int sh[256];
    int t = threadIdx.x;
    int v = (t < NB_SCAN) ? d_bsum[t] : 0;
    sh[t] = v;
    __syncthreads();
    for (int off = 1; off < 256; off <<= 1) {
        int u = (t >= off) ? sh[t - off] : 0;
        __syncthreads();
        sh[t] += u;
        __syncthreads();
    }
    if (t < NB_SCAN) d_boff[t] = sh[t] - v;
    if (t == 255) d_rowptr[N_NODES] = sh[255];
}

__global__ void scan3_kernel() {
    __shared__ int sh[256];
    int t = threadIdx.x;
    int i = blockIdx.x * 256 + t;
    int v = (i < N_NODES) ? d_deg[i] : 0;
    sh[t] = v;
    __syncthreads();
    for (int off = 1; off < 256; off <<= 1) {
        int u = (t >= off) ? sh[t - off] : 0;
        __syncthreads();
        sh[t] += u;
        __syncthreads();
    }
    if (i < N_NODES) d_rowptr[i] = sh[t] - v + d_boff[blockIdx.x];
}

__global__ void scatter_kernel(const float* __restrict__ ea) {
    int e = blockIdx.x * blockDim.x + threadIdx.x;
    if (e >= E_EDGES) return;
    int dn = d_dst[e];
    int pos = d_rowptr[dn] + atomicAdd(&d_fill[dn], 1);
    pos = min(max(pos, 0), E_EDGES - 1);
    d_esrc[pos] = d_src[e];
    const float4* A = (const float4*)&ea[(size_t)e * 16];
    float4* B = (float4*)&d_ea_s[(size_t)pos * 16];
    B[0] = A[0]; B[1] = A[1]; B[2] = A[2]; B[3] = A[3];
}

// ---------------- node GEMM: P[n][256] = in[n][64] @ Wnode + bias ----------------
__global__ __launch_bounds__(256) void node_gemm_kernel(const float* __restrict__ x_in, int layer) {
    __shared__ __align__(16) float sX[64 * 68];
    __shared__ float sB[256];
    __shared__ float sSc[64], sSh[64];
    int t = threadIdx.x;
    int n0 = blockIdx.x * 64;
    const float* __restrict__ src = layer ? d_y0 : x_in;
    const float* __restrict__ Wn = d_Wnode[layer];

    sB[t] = d_bias2[layer][t];
    if (t < 64) {
        sSc[t] = layer ? d_scale[0][t] : 1.f;
        sSh[t] = layer ? d_shift[0][t] : 0.f;
    }
    __syncthreads();
    {
        int n = t >> 2, q = t & 3;
        int node = n0 + n;
        #pragma unroll
        for (int i = 0; i < 4; i++) {
            int k = q * 16 + i * 4;
            float4 v = make_float4(0.f, 0.f, 0.f, 0.f);
            if (node < N_NODES) v = *(const float4*)&src[(size_t)node * 64 + k];
            sX[(k + 0) * 68 + n] = v.x * sSc[k + 0] + sSh[k + 0];
            sX[(k + 1) * 68 + n] = v.y * sSc[k + 1] + sSh[k + 1];
            sX[(k + 2) * 68 + n] = v.z * sSc[k + 2] + sSh[k + 2];
            sX[(k + 3) * 68 + n] = v.w * sSc[k + 3] + sSh[k + 3];
        }
    }
    __syncthreads();

    int tx = t & 31, ty = t >> 5;
    float acc[8][8];
    #pragma unroll
    for (int e = 0; e < 8; e++)
        #pragma unroll
        for (int j = 0; j < 8; j++) acc[e][j] = 0.f;

    #pragma unroll 8
    for (int k = 0; k < 64; k++) {
        float4 w0 = *(const float4*)&Wn[k * 256 + tx * 8];
        float4 w1 = *(const float4*)&Wn[k * 256 + tx * 8 + 4];
        float4 z0 = *(const float4*)&sX[k * 68 + ty * 8];
        float4 z1 = *(const float4*)&sX[k * 68 + ty * 8 + 4];
        float ww[8] = {w0.x, w0.y, w0.z, w0.w, w1.x, w1.y, w1.z, w1.w};
        float zz[8] = {z0.x, z0.y, z0.z, z0.w, z1.x, z1.y, z1.z, z1.w};
        #pragma unroll
        for (int e = 0; e < 8; e++)
            #pragma unroll
            for (int j = 0; j < 8; j++) acc[e][j] += zz[e] * ww[j];
    }

    float b[8];
    #pragma unroll
    for (int j = 0; j < 8; j++) b[j] = sB[tx * 8 + j];
    #pragma unroll
    for (int e = 0; e < 8; e++) {
        int node = n0 + ty * 8 + e;
        if (node < N_NODES) {
            float4 o0 = make_float4(acc[e][0] + b[0], acc[e][1] + b[1], acc[e][2] + b[2], acc[e][3] + b[3]);
            float4 o1 = make_float4(acc[e][4] + b[4], acc[e][5] + b[5], acc[e][6] + b[6], acc[e][7] + b[7]);
            *(float4*)&d_P[(size_t)node * 256 + tx * 8]     = o0;
            *(float4*)&d_P[(size_t)node * 256 + tx * 8 + 4] = o1;
        }
    }
}

// ---------------- CSR consumer: 2 warps per row, 1 channel per lane ----------------
// Warps 2p,2p+1 process the same rows; warp parity selects channels [0,32)/[32,64).
// Depth-2 pipeline on src gather + ea stream. Fused BN partials. No atomics.
__global__ __launch_bounds__(256, 2) void csr_kernel(const float* __restrict__ x_in, int layer) {
    __shared__ float sS[8][32], sQ[8][32];
    const float* __restrict__ WqT = d_WqT[layer];
    float* __restrict__ y = layer ? d_y1 : d_y0;
    int tid = threadIdx.x, warp = tid >> 5, lane = tid & 31;
    int c = ((warp & 1) << 5) + lane;               // channel owned by this lane
    int gpair = (blockIdx.x * 8 + warp) >> 1;       // row stream id
    const int npairs = NB_CSR * 4;

    // per-lane weights: f and s rows, 8 k-pairs each (32 regs)
    uint64_t wf[8], ws[8];
    {
        const uint64_t* WF = (const uint64_t*)&WqT[c * 16];
        const uint64_t* WS = (const uint64_t*)&WqT[(64 + c) * 16];
        #pragma unroll
        for (int k = 0; k < 8; k++) { wf[k] = WF[k]; ws[k] = WS[k]; }
    }
    float rs = 1.f, rh = 0.f;
    if (layer) { rs = d_scale[0][c]; rh = d_shift[0][c]; }

    float st_s = 0.f, st_q = 0.f;

    for (int row = gpair; row < N_NODES; row += npairs) {
        int e0 = d_rowptr[row], e1 = d_rowptr[row + 1];
        float2 dp = *(const float2*)&d_P[(size_t)row * 256 + 2 * c];   // {fd,sd}
        float acc = 0.f;

        if (e0 < e1) {
            int src = d_esrc[e0];
            float2 sp = *(const float2*)&d_P[(size_t)src * 256 + 128 + 2 * c];
            const ulonglong2* Au = (const ulonglong2*)&d_ea_s[(size_t)e0 * 16];
            ulonglong2 u0 = Au[0], u1 = Au[1], u2 = Au[2], u3 = Au[3];

            for (int e = e0; e < e1; e++) {
                float2 csp = sp;
                uint64_t ep[8] = {u0.x, u0.y, u1.x, u1.y, u2.x, u2.y, u3.x, u3.y};
                // clamped prefetch (branchless; last edge reloads itself harmlessly)
                int en = min(e + 1, e1 - 1);
                int ns = d_esrc[en];
                sp = *(const float2*)&d_P[(size_t)ns * 256 + 128 + 2 * c];
                const ulonglong2* An = (const ulonglong2*)&d_ea_s[(size_t)en * 16];
                u0 = An[0]; u1 = An[1]; u2 = An[2]; u3 = An[3];

                uint64_t qf = 0, qs = 0;
                #pragma unroll
                for (int k = 0; k < 8; k++) {
                    qf = fma2(wf[k], ep[k], qf);
                    qs = fma2(ws[k], ep[k], qs);
                }
                float2 hf = unpack2(qf), hs = unpack2(qs);
                float f = dp.x + csp.x + (hf.x + hf.y);
                float s = dp.y + csp.y + (hs.x + hs.y);
                acc += sigmoid_f(f) * softplus_f(s);
            }
        }
        float xv;
        if (layer) {
            float tv = d_y0[(size_t)row * 64 + c];
            xv = tv * rs + rh;
        } else {
            xv = x_in[(size_t)row * 64 + c];
        }
        float o = xv + acc;
        y[(size_t)row * 64 + c] = o;
        st_s += o;
        st_q = fmaf(o, o, st_q);
    }

    sS[warp][lane] = st_s;
    sQ[warp][lane] = st_q;
    __syncthreads();
    if (tid < 64) {
        int cc = tid, par = cc >> 5, l = cc & 31;
        d_psum[blockIdx.x * 64 + cc] = sS[par][l] + sS[par + 2][l] + sS[par + 4][l] + sS[par + 6][l];
        d_psq[blockIdx.x * 64 + cc]  = sQ[par][l] + sQ[par + 2][l] + sQ[par + 4][l] + sQ[par + 6][l];
    }
}

// ---------------- finalize BN stats from csr-block partials ----------------
__global__ __launch_bounds__(256) void finalize_stats_kernel(int layer, const float* __restrict__ gamma,
                                                             const float* __restrict__ beta) {
    __shared__ double shS[256], shQ[256];
    int t = threadIdx.x;
    int c = t & 63, sl = t >> 6;
    double s = 0.0, q = 0.0;
    for (int b = sl; b < NB_CSR; b += 4) {
        s += (double)d_psum[b * 64 + c];
        q += (double)d_psq[b * 64 + c];
    }
    shS[t] = s; shQ[t] = q;
    __syncthreads();
    if (t < 64) {
        double S = shS[t] + shS[t + 64] + shS[t + 128] + shS[t + 192];
        double Q = shQ[t] + shQ[t + 64] + shQ[t + 128] + shQ[t + 192];
        double m = S / (double)N_NODES;
        double v = Q / (double)N_NODES - m * m;
        double sc = (double)gamma[c] * rsqrt(v + 1e-5);
        d_scale[layer][c] = (float)sc;
        d_shift[layer][c] = (float)((double)beta[c] - m * sc);
    }
}

// ---------------- graph boundaries via binary search ----------------
__global__ void bounds_kernel(const void* __restrict__ batch_raw) {
    int g = threadIdx.x;
    if (g > 64) return;
    const int b64 = d_b64;
    const long long* bL = (const long long*)batch_raw;
    const int*       bI = (const int*)batch_raw;
    int lo = 0, hi = N_NODES;
    while (lo < hi) {
        int mid = (lo + hi) >> 1;
        long long bv = b64 ? bL[mid] : (long long)bI[mid];
        if (bv < (long long)g) lo = mid + 1; else hi = mid;
    }
    d_bound[g] = lo;
}

// BN(layer1) fused with global-mean-pool: one block per graph
__global__ __launch_bounds__(256) void pool_kernel(float* __restrict__ out) {
    __shared__ float sred[256];
    int g = blockIdx.x;
    int t = threadIdx.x;
    int c = t & 63, sub = t >> 6;
    int r0 = d_bound[g], r1 = d_bound[g + 1];
    float sc = d_scale[1][c], sh = d_shift[1][c];
    float acc = 0.f;
    for (int r = r0 + sub; r < r1; r += 4)
        acc += d_y1[(size_t)r * 64 + c] * sc + sh;
    sred[t] = acc;
    __syncthreads();
    if (t < 128) sred[t] += sred[t + 128];
    __syncthreads();
    if (t < 64) {
        float total = sred[t] + sred[t + 64];
        float cnt = (float)(r1 - r0);
        out[g * 64 + c] = total / fmaxf(cnt, 1.f);
    }
}

// ---------------- launch ----------------
extern "C" void kernel_launch(void* const* d_in, const int* in_sizes, int n_in,
                              void* d_out, int out_size) {
    const float* x     = (const float*)d_in[0];
    const void*  ei    = d_in[1];
    const float* ea    = (const float*)d_in[2];
    const void*  batch = d_in[3];
    const float *Wf0 = (const float*)d_in[4],  *bf0 = (const float*)d_in[5];
    const float *Ws0 = (const float*)d_in[6],  *bs0 = (const float*)d_in[7];
    const float *g0  = (const float*)d_in[8],  *be0 = (const float*)d_in[9];
    const float *Wf1 = (const float*)d_in[10], *bf1 = (const float*)d_in[11];
    const float *Ws1 = (const float*)d_in[12], *bs1 = (const float*)d_in[13];
    const float *g1  = (const float*)d_in[14], *be1 = (const float*)d_in[15];
    float* out = (float*)d_out;

    const int nodeBlocks = (N_NODES + 63) / 64;          // 782
    const int edgeGrid   = (E_EDGES + 255) / 256;        // 3125

    zero_detect_kernel<<<NB_SCAN, 256>>>((const int*)ei, (const int*)batch);
    prep_kernel<<<512, 256>>>(ei, Wf0, Ws0, bf0, bs0, Wf1, Ws1, bf1, bs1);
    scan1_kernel<<<NB_SCAN, 256>>>();
    scan2_kernel<<<1, 256>>>();
    scan3_kernel<<<NB_SCAN, 256>>>();
    scatter_kernel<<<edgeGrid, 256>>>(ea);
    bounds_kernel<<<1, 128>>>(batch);

    // layer 0 (stats fused into csr)
    node_gemm_kernel<<<nodeBlocks, 256>>>(x, 0);
    csr_kernel<<<NB_CSR, 256>>>(x, 0);
    finalize_stats_kernel<<<1, 256>>>(0, g0, be0);

    // layer 1 (BN0 folded into node_gemm input + csr residual)
    node_gemm_kernel<<<nodeBlocks, 256>>>(x, 1);
    csr_kernel<<<NB_CSR, 256>>>(x, 1);
    finalize_stats_kernel<<<1, 256>>>(1, g1, be1);

    // pool + output
    pool_kernel<<<64, 256>>>(out);
}